// round 1
// baseline (speedup 1.0000x reference)
#include <cuda_runtime.h>
#include <cuda_bf16.h>
#include <math.h>
#include <stdint.h>

#define B 2
#define P 512
#define C 21
#define REG 5
#define DET 100
#define NGRP (B*(C-1))          // 40
#define NPROP (B*P)             // 1024
#define SCORE_THRESH 0.05f
#define NMS_THR 0.5f
#define BBOX_CLIP 4.135166556742356f   // log(1000/16)
#define DEG2RAD 0.017453292519943295f
#define RAD2DEG 57.29577951308232f
#define IMW_M1 1023.0f
#define IMH_M1 799.0f
#define QCAP 131072

// ---------------- device scratch ----------------
__device__ float g_scores[NPROP * C];            // softmax scores
__device__ float g_props[NPROP * C * 5];         // decoded rotated boxes
__device__ float g_bb[NPROP * C * 4];            // clipped axis-aligned boxes
__device__ float g_sc_s[NGRP * P];               // sorted masked scores
__device__ float g_pr_s[NGRP * P * 5];           // sorted proposals
__device__ float g_bx_s[NGRP * P * 4];           // sorted aabb boxes
__device__ float g_msk[B * (C-1) * P];           // post-NMS masked scores
__device__ int   g_queue[NGRP * QCAP];           // candidate pair queue

// ---------------- kernel 1: softmax + decode + bb ----------------
__global__ void k1_decode(const float* __restrict__ logits,
                          const float* __restrict__ regr,
                          const float* __restrict__ rrects)
{
    int n = blockIdx.x;        // proposal row 0..1023
    int t = threadIdx.x;       // 0..31

    float x = (t < C) ? logits[n * C + t] : -INFINITY;
    float m = x;
    #pragma unroll
    for (int o = 16; o; o >>= 1) m = fmaxf(m, __shfl_xor_sync(0xffffffffu, m, o));
    float e = (t < C) ? expf(x - m) : 0.0f;
    float ssum = e;
    #pragma unroll
    for (int o = 16; o; o >>= 1) ssum += __shfl_xor_sync(0xffffffffu, ssum, o);
    float score = e / ssum;
    if (t < C) g_scores[n * C + t] = score;

    // anchor
    float axc = rrects[n*5+0], ayc = rrects[n*5+1];
    float aw  = rrects[n*5+2], ah  = rrects[n*5+3];
    float aa  = rrects[n*5+4];

    if (t < C) {
        const float* d = &regr[n * C * REG + t * REG];
        float dx = d[0] / 10.0f;
        float dy = d[1] / 10.0f;
        float dw = fminf(d[2] / 5.0f, BBOX_CLIP);
        float dh = fminf(d[3] / 5.0f, BBOX_CLIP);
        float da = d[4] / 3.0f;

        float px = dx * aw + axc;
        float py = dy * ah + ayc;
        float pw = expf(dw) * aw;
        float ph = expf(dh) * ah;
        float pa = da * RAD2DEG + aa;

        float* pp = &g_props[(n * C + t) * 5];
        pp[0]=px; pp[1]=py; pp[2]=pw; pp[3]=ph; pp[4]=pa;

        float th = pa * DEG2RAD;
        float cth = cosf(th), sth = sinf(th);
        float hx = pw * 0.5f, hy = ph * 0.5f;
        float ox[4] = {-hx, hx, hx, -hx};
        float oy[4] = {-hy, -hy, hy, hy};
        float mnx =  1e30f, mny =  1e30f, mxx = -1e30f, mxy = -1e30f;
        #pragma unroll
        for (int i = 0; i < 4; i++) {
            float cx = px + cth*ox[i] - sth*oy[i];
            float cy = py + sth*ox[i] + cth*oy[i];
            mnx = fminf(mnx, cx); mxx = fmaxf(mxx, cx);
            mny = fminf(mny, cy); mxy = fmaxf(mxy, cy);
        }
        float* bb = &g_bb[(n * C + t) * 4];
        bb[0] = fminf(fmaxf(mnx, 0.0f), IMW_M1);
        bb[1] = fminf(fmaxf(mny, 0.0f), IMH_M1);
        bb[2] = fminf(fmaxf(mxx, 0.0f), IMW_M1);
        bb[3] = fminf(fmaxf(mxy, 0.0f), IMH_M1);
    }
}

// ---------------- kernel 2: per-group bitonic sort (desc, tie idx asc) ------
__global__ void k2_sort()
{
    int g = blockIdx.x;                 // 0..39
    int b = g / (C-1);
    int cls = g % (C-1) + 1;
    int p = threadIdx.x;                // 0..511

    __shared__ float sv[P];
    __shared__ int   si[P];

    int n = b * P + p;
    float s = g_scores[n * C + cls];
    float masked = (s > SCORE_THRESH) ? s : -1.0f;
    sv[p] = masked; si[p] = p;
    __syncthreads();

    for (int k = 2; k <= P; k <<= 1) {
        for (int j = k >> 1; j > 0; j >>= 1) {
            int ixj = p ^ j;
            if (ixj > p) {
                float a = sv[p], bq = sv[ixj];
                int ia = si[p], ib = si[ixj];
                bool before = (a > bq) || (a == bq && ia < ib);
                bool dir = ((p & k) == 0);
                if (dir ? !before : before) {
                    sv[p] = bq; sv[ixj] = a;
                    si[p] = ib; si[ixj] = ia;
                }
            }
            __syncthreads();
        }
    }

    int op = si[p];
    float val = sv[p];
    g_sc_s[g * P + p] = val;
    int src = (b * P + op) * C + cls;
    #pragma unroll
    for (int k = 0; k < 5; k++) g_pr_s[(g * P + p) * 5 + k] = g_props[src * 5 + k];
    #pragma unroll
    for (int k = 0; k < 4; k++) g_bx_s[(g * P + p) * 4 + k] = g_bb[src * 4 + k];
}

// ---------------- exact quad-quad intersection area (matches reference) -----
__device__ float inter_area(const float* __restrict__ p1x, const float* __restrict__ p1y,
                            const float* __restrict__ p2x, const float* __restrict__ p2y)
{
    float px[8], py[8];
    #pragma unroll
    for (int i = 0; i < 4; i++) { px[i] = p1x[i]; py[i] = p1y[i]; }
    int n = 4;

    for (int k = 0; k < 4; k++) {
        float ax = p2x[k], ay = p2y[k];
        int k1 = (k + 1) & 3;
        float dx = p2x[k1] - ax, dy = p2y[k1] - ay;
        float qx[8], qy[8];
        int m = 0;
        for (int i = 0; i < n; i++) {
            float sx = px[i], sy = py[i];
            int ei = (i + 1 == n) ? 0 : (i + 1);
            float ex = px[ei], ey = py[ei];
            float cs = dx * (sy - ay) - dy * (sx - ax);
            float ce = dx * (ey - ay) - dy * (ex - ax);
            float denom = cs - ce;
            float t = cs / ((fabsf(denom) > 1e-12f) ? denom : 1e-12f);
            float ipx = sx + t * (ex - sx);
            float ipy = sy + t * (ey - sy);
            bool s_in = (cs >= 0.0f), e_in = (ce >= 0.0f);
            if (s_in != e_in) { int mm = m < 7 ? m : 7; qx[mm] = ipx; qy[mm] = ipy; m++; }
            if (e_in)         { int mm = m < 7 ? m : 7; qx[mm] = ex;  qy[mm] = ey;  m++; }
        }
        if (m > 8) m = 8;
        n = m;
        for (int i = 0; i < n; i++) { px[i] = qx[i]; py[i] = qy[i]; }
    }
    if (n < 3) return 0.0f;
    float acc = 0.0f;
    for (int i = 0; i < n; i++) {
        int k2 = (i + 1 == n) ? 0 : (i + 1);
        acc += px[i] * py[k2] - px[k2] * py[i];
    }
    return 0.5f * fabsf(acc);
}

// ---------------- kernel 3: rotated NMS per group ----------------
__global__ void k3_nms()
{
    int g = blockIdx.x;          // 0..39
    int tid = threadIdx.x;       // 0..511

    extern __shared__ float sm3[];
    float* ptsx  = sm3;                 // 512*4
    float* ptsy  = ptsx + P * 4;        // 512*4
    float* bminx = ptsy + P * 4;        // 512
    float* bminy = bminx + P;
    float* bmaxx = bminy + P;
    float* bmaxy = bmaxx + P;
    float* areaS = bmaxy + P;           // 512
    unsigned* sup = (unsigned*)(areaS + P);  // 512*16
    __shared__ int qcnt;
    __shared__ unsigned keepM[16];
    __shared__ int Vsh;

    // corner points + aabb + area
    const float* rr = &g_pr_s[(g * P + tid) * 5];
    float xc = rr[0], yc = rr[1], w = rr[2], h = rr[3], ang = rr[4];
    float th = ang * DEG2RAD;
    float cth = cosf(th), sth = sinf(th);
    float hx = w * 0.5f, hy = h * 0.5f;
    float oxs[4] = {-hx, hx, hx, -hx};
    float oys[4] = {-hy, -hy, hy, hy};
    float mnx = 1e30f, mny = 1e30f, mxx = -1e30f, mxy = -1e30f;
    #pragma unroll
    for (int i = 0; i < 4; i++) {
        float cx = xc + cth * oxs[i] - sth * oys[i];
        float cy = yc + sth * oxs[i] + cth * oys[i];
        ptsx[tid * 4 + i] = cx;
        ptsy[tid * 4 + i] = cy;
        mnx = fminf(mnx, cx); mxx = fmaxf(mxx, cx);
        mny = fminf(mny, cy); mxy = fmaxf(mxy, cy);
    }
    bminx[tid] = mnx; bmaxx[tid] = mxx;
    bminy[tid] = mny; bmaxy[tid] = mxy;
    areaS[tid] = w * h;
    #pragma unroll
    for (int k = 0; k < 16; k++) sup[tid * 16 + k] = 0u;

    float sc = g_sc_s[g * P + tid];
    bool valid = sc > SCORE_THRESH;
    int V = __syncthreads_count(valid);   // valid entries are a sorted prefix
    if (tid == 0) { qcnt = 0; Vsh = V; }
    __syncthreads();

    // phase 1: AABB precheck -> pair queue
    int* queue = &g_queue[g * QCAP];
    long long M = (long long)V * (V - 1) / 2;
    for (long long t = tid; t < M; t += blockDim.x) {
        int i = (int)((sqrtf(8.0f * (float)t + 1.0f) + 1.0f) * 0.5f);
        while ((long long)i * (i - 1) / 2 > t) i--;
        while ((long long)(i + 1) * i / 2 <= t) i++;
        int j = (int)(t - (long long)i * (i - 1) / 2);
        bool ov = !(bmaxx[i] < bminx[j] || bmaxx[j] < bminx[i] ||
                    bmaxy[i] < bminy[j] || bmaxy[j] < bminy[i]);
        if (ov) {
            int pos = atomicAdd(&qcnt, 1);
            queue[pos] = (i << 16) | j;
        }
    }
    __syncthreads();

    // phase 2: dense exact IoU over surviving pairs
    int nq = qcnt;
    for (int q = tid; q < nq; q += blockDim.x) {
        int ij = queue[q];
        int i = ij >> 16, j = ij & 0xffff;
        float inter = inter_area(&ptsx[i * 4], &ptsy[i * 4], &ptsx[j * 4], &ptsy[j * 4]);
        float iou = inter / (areaS[i] + areaS[j] - inter + 1e-8f);
        if (iou > NMS_THR) atomicOr(&sup[i * 16 + (j >> 5)], 1u << (j & 31));
    }
    __syncthreads();

    // phase 3: greedy scan (warp 0, one keep-word per lane<16)
    if (tid < 32) {
        unsigned kw = 0;
        int VV = Vsh;
        for (int i = 0; i < VV; i++) {
            unsigned srow = (tid < 16) ? sup[i * 16 + tid] : 0u;
            bool any = __any_sync(0xffffffffu, (kw & srow) != 0u);
            if (!any && tid == (i >> 5)) kw |= 1u << (i & 31);
        }
        if (tid < 16) keepM[tid] = kw;
    }
    __syncthreads();

    bool kept = (tid < Vsh) && ((keepM[tid >> 5] >> (tid & 31)) & 1u);
    g_msk[g * P + tid] = kept ? sc : -1.0f;
}

// ---------------- kernel 4: per-image top-100 + output ----------------
#define SORTN 16384
__global__ void k4_topk(float* __restrict__ out)
{
    int b = blockIdx.x;
    int tid = threadIdx.x;
    int nthr = blockDim.x;

    extern __shared__ char sm4[];
    float* v  = (float*)sm4;
    int*   id = (int*)(v + SORTN);

    int total = (C - 1) * P;   // 10240
    for (int f = tid; f < SORTN; f += nthr) {
        if (f < total) { v[f] = g_msk[b * total + f]; id[f] = f; }
        else           { v[f] = -1e30f;               id[f] = f; }
    }
    __syncthreads();

    for (int k = 2; k <= SORTN; k <<= 1) {
        for (int j = k >> 1; j > 0; j >>= 1) {
            for (int idx = tid; idx < SORTN; idx += nthr) {
                int ixj = idx ^ j;
                if (ixj > idx) {
                    float a = v[idx], bq = v[ixj];
                    int ia = id[idx], ib = id[ixj];
                    bool before = (a > bq) || (a == bq && ia < ib);
                    bool dir = ((idx & k) == 0);
                    if (dir ? !before : before) {
                        v[idx] = bq; v[ixj] = a;
                        id[idx] = ib; id[ixj] = ia;
                    }
                }
            }
            __syncthreads();
        }
    }

    // output layout (float32): bb [B,DET,4] | rr [B,DET,5] | sc [B,DET] | lab [B,DET]
    for (int k = tid; k < DET; k += nthr) {
        float val = v[k];
        int fi = id[k];
        bool ok = val > 0.0f;
        int cls = fi / P + 1;
        int gi = b * total + fi;   // index into g_bx_s/g_pr_s flat
        int o = b * DET + k;
        #pragma unroll
        for (int jj = 0; jj < 4; jj++)
            out[o * 4 + jj] = ok ? g_bx_s[gi * 4 + jj] : 0.0f;
        #pragma unroll
        for (int jj = 0; jj < 5; jj++)
            out[B * DET * 4 + o * 5 + jj] = ok ? g_pr_s[gi * 5 + jj] : 0.0f;
        out[B * DET * 9 + o] = ok ? val : 0.0f;
        out[B * DET * 10 + o] = ok ? (float)cls : 0.0f;
    }
}

// ---------------- launch ----------------
extern "C" void kernel_launch(void* const* d_in, const int* in_sizes, int n_in,
                              void* d_out, int out_size)
{
    const float* logits = (const float*)d_in[0];
    const float* regr   = (const float*)d_in[1];
    const float* rrects = (const float*)d_in[2];
    float* out = (float*)d_out;

    const int SMEM3 = (P*4*2 + P*5) * (int)sizeof(float) + P*16*(int)sizeof(unsigned);
    const int SMEM4 = SORTN * (int)(sizeof(float) + sizeof(int));
    cudaFuncSetAttribute(k3_nms,  cudaFuncAttributeMaxDynamicSharedMemorySize, SMEM3);
    cudaFuncSetAttribute(k4_topk, cudaFuncAttributeMaxDynamicSharedMemorySize, SMEM4);

    k1_decode<<<NPROP, 32>>>(logits, regr, rrects);
    k2_sort<<<NGRP, P>>>();
    k3_nms<<<NGRP, P, SMEM3>>>();
    k4_topk<<<B, 1024, SMEM4>>>(out);
}

// round 2
// speedup vs baseline: 5.8567x; 5.8567x over previous
#include <cuda_runtime.h>
#include <cuda_bf16.h>
#include <math.h>
#include <stdint.h>

#define B 2
#define P 512
#define C 21
#define REG 5
#define DET 100
#define NGRP (B*(C-1))          // 40
#define NPROP (B*P)             // 1024
#define SCORE_THRESH 0.05f
#define NMS_THR 0.5f
#define BBOX_CLIP 4.135166556742356f   // log(1000/16)
#define DEG2RAD 0.017453292519943295f
#define RAD2DEG 57.29577951308232f
#define IMW_M1 1023.0f
#define IMH_M1 799.0f
#define QCAP 131072

// ---------------- device scratch ----------------
__device__ float g_scores[NPROP * C];            // softmax scores
__device__ float g_props[NPROP * C * 5];         // decoded rotated boxes
__device__ float g_bb[NPROP * C * 4];            // clipped axis-aligned boxes
__device__ float g_sc_s[NGRP * P];               // sorted masked scores
__device__ float g_pr_s[NGRP * P * 5];           // sorted proposals
__device__ float g_bx_s[NGRP * P * 4];           // sorted aabb boxes
__device__ float g_msk[B * (C-1) * P];           // post-NMS masked scores
__device__ int   g_queue[NGRP * QCAP];           // candidate pair queue

// ---------------- kernel 1: softmax + decode + bb ----------------
__global__ void k1_decode(const float* __restrict__ logits,
                          const float* __restrict__ regr,
                          const float* __restrict__ rrects)
{
    int n = blockIdx.x;        // proposal row 0..1023
    int t = threadIdx.x;       // 0..31

    float x = (t < C) ? logits[n * C + t] : -INFINITY;
    float m = x;
    #pragma unroll
    for (int o = 16; o; o >>= 1) m = fmaxf(m, __shfl_xor_sync(0xffffffffu, m, o));
    float e = (t < C) ? expf(x - m) : 0.0f;
    float ssum = e;
    #pragma unroll
    for (int o = 16; o; o >>= 1) ssum += __shfl_xor_sync(0xffffffffu, ssum, o);
    float score = e / ssum;
    if (t < C) g_scores[n * C + t] = score;

    // anchor
    float axc = rrects[n*5+0], ayc = rrects[n*5+1];
    float aw  = rrects[n*5+2], ah  = rrects[n*5+3];
    float aa  = rrects[n*5+4];

    if (t < C) {
        const float* d = &regr[n * C * REG + t * REG];
        float dx = d[0] / 10.0f;
        float dy = d[1] / 10.0f;
        float dw = fminf(d[2] / 5.0f, BBOX_CLIP);
        float dh = fminf(d[3] / 5.0f, BBOX_CLIP);
        float da = d[4] / 3.0f;

        float px = dx * aw + axc;
        float py = dy * ah + ayc;
        float pw = expf(dw) * aw;
        float ph = expf(dh) * ah;
        float pa = da * RAD2DEG + aa;

        float* pp = &g_props[(n * C + t) * 5];
        pp[0]=px; pp[1]=py; pp[2]=pw; pp[3]=ph; pp[4]=pa;

        float th = pa * DEG2RAD;
        float cth = cosf(th), sth = sinf(th);
        float hx = pw * 0.5f, hy = ph * 0.5f;
        float ox[4] = {-hx, hx, hx, -hx};
        float oy[4] = {-hy, -hy, hy, hy};
        float mnx =  1e30f, mny =  1e30f, mxx = -1e30f, mxy = -1e30f;
        #pragma unroll
        for (int i = 0; i < 4; i++) {
            float cx = px + cth*ox[i] - sth*oy[i];
            float cy = py + sth*ox[i] + cth*oy[i];
            mnx = fminf(mnx, cx); mxx = fmaxf(mxx, cx);
            mny = fminf(mny, cy); mxy = fmaxf(mxy, cy);
        }
        float* bb = &g_bb[(n * C + t) * 4];
        bb[0] = fminf(fmaxf(mnx, 0.0f), IMW_M1);
        bb[1] = fminf(fmaxf(mny, 0.0f), IMH_M1);
        bb[2] = fminf(fmaxf(mxx, 0.0f), IMW_M1);
        bb[3] = fminf(fmaxf(mxy, 0.0f), IMH_M1);
    }
}

// ---------------- kernel 2: per-group bitonic sort (desc, tie idx asc) ------
__global__ void k2_sort()
{
    int g = blockIdx.x;                 // 0..39
    int b = g / (C-1);
    int cls = g % (C-1) + 1;
    int p = threadIdx.x;                // 0..511

    __shared__ float sv[P];
    __shared__ int   si[P];

    int n = b * P + p;
    float s = g_scores[n * C + cls];
    float masked = (s > SCORE_THRESH) ? s : -1.0f;
    sv[p] = masked; si[p] = p;
    __syncthreads();

    for (int k = 2; k <= P; k <<= 1) {
        for (int j = k >> 1; j > 0; j >>= 1) {
            int ixj = p ^ j;
            if (ixj > p) {
                float a = sv[p], bq = sv[ixj];
                int ia = si[p], ib = si[ixj];
                bool before = (a > bq) || (a == bq && ia < ib);
                bool dir = ((p & k) == 0);
                if (dir ? !before : before) {
                    sv[p] = bq; sv[ixj] = a;
                    si[p] = ib; si[ixj] = ia;
                }
            }
            __syncthreads();
        }
    }

    int op = si[p];
    float val = sv[p];
    g_sc_s[g * P + p] = val;
    int src = (b * P + op) * C + cls;
    #pragma unroll
    for (int k = 0; k < 5; k++) g_pr_s[(g * P + p) * 5 + k] = g_props[src * 5 + k];
    #pragma unroll
    for (int k = 0; k < 4; k++) g_bx_s[(g * P + p) * 4 + k] = g_bb[src * 4 + k];
}

// ---------------- exact quad-quad intersection area (matches reference) -----
__device__ float inter_area(const float* __restrict__ p1x, const float* __restrict__ p1y,
                            const float* __restrict__ p2x, const float* __restrict__ p2y)
{
    float px[8], py[8];
    #pragma unroll
    for (int i = 0; i < 4; i++) { px[i] = p1x[i]; py[i] = p1y[i]; }
    int n = 4;

    for (int k = 0; k < 4; k++) {
        float ax = p2x[k], ay = p2y[k];
        int k1 = (k + 1) & 3;
        float dx = p2x[k1] - ax, dy = p2y[k1] - ay;
        float qx[8], qy[8];
        int m = 0;
        for (int i = 0; i < n; i++) {
            float sx = px[i], sy = py[i];
            int ei = (i + 1 == n) ? 0 : (i + 1);
            float ex = px[ei], ey = py[ei];
            float cs = dx * (sy - ay) - dy * (sx - ax);
            float ce = dx * (ey - ay) - dy * (ex - ax);
            float denom = cs - ce;
            float t = cs / ((fabsf(denom) > 1e-12f) ? denom : 1e-12f);
            float ipx = sx + t * (ex - sx);
            float ipy = sy + t * (ey - sy);
            bool s_in = (cs >= 0.0f), e_in = (ce >= 0.0f);
            if (s_in != e_in) { int mm = m < 7 ? m : 7; qx[mm] = ipx; qy[mm] = ipy; m++; }
            if (e_in)         { int mm = m < 7 ? m : 7; qx[mm] = ex;  qy[mm] = ey;  m++; }
        }
        if (m > 8) m = 8;
        n = m;
        for (int i = 0; i < n; i++) { px[i] = qx[i]; py[i] = qy[i]; }
    }
    if (n < 3) return 0.0f;
    float acc = 0.0f;
    for (int i = 0; i < n; i++) {
        int k2 = (i + 1 == n) ? 0 : (i + 1);
        acc += px[i] * py[k2] - px[k2] * py[i];
    }
    return 0.5f * fabsf(acc);
}

// ---------------- kernel 3: rotated NMS per group ----------------
__global__ void k3_nms()
{
    int g = blockIdx.x;          // 0..39
    int tid = threadIdx.x;       // 0..511

    extern __shared__ float sm3[];
    float* ptsx  = sm3;                 // 512*4
    float* ptsy  = ptsx + P * 4;        // 512*4
    float* bminx = ptsy + P * 4;        // 512
    float* bminy = bminx + P;
    float* bmaxx = bminy + P;
    float* bmaxy = bmaxx + P;
    float* areaS = bmaxy + P;           // 512
    unsigned* sup = (unsigned*)(areaS + P);  // 512*16
    __shared__ int qcnt;
    __shared__ unsigned keepM[16];
    __shared__ int Vsh;

    // corner points + aabb + area
    const float* rr = &g_pr_s[(g * P + tid) * 5];
    float xc = rr[0], yc = rr[1], w = rr[2], h = rr[3], ang = rr[4];
    float th = ang * DEG2RAD;
    float cth = cosf(th), sth = sinf(th);
    float hx = w * 0.5f, hy = h * 0.5f;
    float oxs[4] = {-hx, hx, hx, -hx};
    float oys[4] = {-hy, -hy, hy, hy};
    float mnx = 1e30f, mny = 1e30f, mxx = -1e30f, mxy = -1e30f;
    #pragma unroll
    for (int i = 0; i < 4; i++) {
        float cx = xc + cth * oxs[i] - sth * oys[i];
        float cy = yc + sth * oxs[i] + cth * oys[i];
        ptsx[tid * 4 + i] = cx;
        ptsy[tid * 4 + i] = cy;
        mnx = fminf(mnx, cx); mxx = fmaxf(mxx, cx);
        mny = fminf(mny, cy); mxy = fmaxf(mxy, cy);
    }
    bminx[tid] = mnx; bmaxx[tid] = mxx;
    bminy[tid] = mny; bmaxy[tid] = mxy;
    areaS[tid] = w * h;
    #pragma unroll
    for (int k = 0; k < 16; k++) sup[tid * 16 + k] = 0u;

    float sc = g_sc_s[g * P + tid];
    bool valid = sc > SCORE_THRESH;
    int V = __syncthreads_count(valid);   // valid entries are a sorted prefix
    if (tid == 0) { qcnt = 0; Vsh = V; }
    __syncthreads();

    // phase 1: AABB precheck -> pair queue
    int* queue = &g_queue[g * QCAP];
    long long M = (long long)V * (V - 1) / 2;
    for (long long t = tid; t < M; t += blockDim.x) {
        int i = (int)((sqrtf(8.0f * (float)t + 1.0f) + 1.0f) * 0.5f);
        while ((long long)i * (i - 1) / 2 > t) i--;
        while ((long long)(i + 1) * i / 2 <= t) i++;
        int j = (int)(t - (long long)i * (i - 1) / 2);
        bool ov = !(bmaxx[i] < bminx[j] || bmaxx[j] < bminx[i] ||
                    bmaxy[i] < bminy[j] || bmaxy[j] < bminy[i]);
        if (ov) {
            int pos = atomicAdd(&qcnt, 1);
            queue[pos] = (i << 16) | j;
        }
    }
    __syncthreads();

    // phase 2: dense exact IoU over surviving pairs
    int nq = qcnt;
    for (int q = tid; q < nq; q += blockDim.x) {
        int ij = queue[q];
        int i = ij >> 16, j = ij & 0xffff;
        float inter = inter_area(&ptsx[i * 4], &ptsy[i * 4], &ptsx[j * 4], &ptsy[j * 4]);
        float iou = inter / (areaS[i] + areaS[j] - inter + 1e-8f);
        if (iou > NMS_THR) atomicOr(&sup[i * 16 + (j >> 5)], 1u << (j & 31));
    }
    __syncthreads();

    // phase 3: greedy scan (warp 0, one keep-word per lane<16)
    if (tid < 32) {
        unsigned kw = 0;
        int VV = Vsh;
        for (int i = 0; i < VV; i++) {
            unsigned srow = (tid < 16) ? sup[i * 16 + tid] : 0u;
            bool any = __any_sync(0xffffffffu, (kw & srow) != 0u);
            if (!any && tid == (i >> 5)) kw |= 1u << (i & 31);
        }
        if (tid < 16) keepM[tid] = kw;
    }
    __syncthreads();

    bool kept = (tid < Vsh) && ((keepM[tid >> 5] >> (tid & 31)) & 1u);
    g_msk[g * P + tid] = kept ? sc : -1.0f;
}

// ---------------- kernel 4: radix-threshold top-100 + output ----------------
#define K4_THREADS 1024
#define K4_PER (( (C-1)*P + K4_THREADS - 1) / K4_THREADS)   // 10
#define CANDCAP 256

__global__ void k4_topk(float* __restrict__ out)
{
    int b = blockIdx.x;
    int tid = threadIdx.x;
    const int TOT = (C - 1) * P;   // 10240
    int lane = tid & 31;

    // hold everything in registers
    float v[K4_PER];
    unsigned key[K4_PER];
    #pragma unroll
    for (int i = 0; i < K4_PER; i++) {
        int f = tid + i * K4_THREADS;
        float x = (f < TOT) ? g_msk[b * TOT + f] : -1e30f;
        v[i] = x;
        unsigned bb = __float_as_uint(x);
        key[i] = bb ^ ((bb & 0x80000000u) ? 0xFFFFFFFFu : 0x80000000u);
    }

    __shared__ int cnt;
    __shared__ int ncand;
    __shared__ float cv[CANDCAP];
    __shared__ int   ci[CANDCAP];

    // binary search: largest threshold K with count(key >= K) >= DET
    unsigned cur = 0u;
    for (int bit = 31; bit >= 0; bit--) {
        unsigned trial = cur | (1u << bit);
        if (tid == 0) cnt = 0;
        __syncthreads();
        int c = 0;
        #pragma unroll
        for (int i = 0; i < K4_PER; i++) c += (key[i] >= trial);
        #pragma unroll
        for (int o = 16; o; o >>= 1) c += __shfl_xor_sync(0xffffffffu, c, o);
        if (lane == 0 && c) atomicAdd(&cnt, c);
        __syncthreads();
        if (cnt >= DET) cur = trial;
        __syncthreads();
    }
    unsigned kthr = cur;   // key of the DET-th largest value

    // collect candidates: key >= kthr AND positive value
    if (tid == 0) ncand = 0;
    __syncthreads();
    #pragma unroll
    for (int i = 0; i < K4_PER; i++) {
        if (key[i] >= kthr && v[i] > 0.0f) {
            int p = atomicAdd(&ncand, 1);
            if (p < CANDCAP) { cv[p] = v[i]; ci[p] = tid + i * K4_THREADS; }
        }
    }
    __syncthreads();
    int nc = min(ncand, CANDCAP);
    // pad
    for (int f = tid; f < CANDCAP; f += K4_THREADS) {
        if (f >= nc) { cv[f] = -1e30f; ci[f] = 0x7fffffff; }
    }
    __syncthreads();

    // bitonic sort 256 candidates desc by (value, idx asc)
    for (int k = 2; k <= CANDCAP; k <<= 1) {
        for (int j = k >> 1; j > 0; j >>= 1) {
            if (tid < CANDCAP) {
                int ixj = tid ^ j;
                if (ixj > tid) {
                    float a = cv[tid], bq = cv[ixj];
                    int ia = ci[tid], ib = ci[ixj];
                    bool before = (a > bq) || (a == bq && ia < ib);
                    bool dir = ((tid & k) == 0);
                    if (dir ? !before : before) {
                        cv[tid] = bq; cv[ixj] = a;
                        ci[tid] = ib; ci[ixj] = ia;
                    }
                }
            }
            __syncthreads();
        }
    }

    // output layout (float32): bb [B,DET,4] | rr [B,DET,5] | sc [B,DET] | lab [B,DET]
    for (int k = tid; k < DET; k += K4_THREADS) {
        float val = (k < nc) ? cv[k] : -1.0f;
        int fi = (k < nc) ? ci[k] : 0;
        bool ok = val > 0.0f;
        int cls = fi / P + 1;
        int gi = b * TOT + fi;
        int o = b * DET + k;
        #pragma unroll
        for (int jj = 0; jj < 4; jj++)
            out[o * 4 + jj] = ok ? g_bx_s[gi * 4 + jj] : 0.0f;
        #pragma unroll
        for (int jj = 0; jj < 5; jj++)
            out[B * DET * 4 + o * 5 + jj] = ok ? g_pr_s[gi * 5 + jj] : 0.0f;
        out[B * DET * 9 + o] = ok ? val : 0.0f;
        out[B * DET * 10 + o] = ok ? (float)cls : 0.0f;
    }
}

// ---------------- launch ----------------
extern "C" void kernel_launch(void* const* d_in, const int* in_sizes, int n_in,
                              void* d_out, int out_size)
{
    const float* logits = (const float*)d_in[0];
    const float* regr   = (const float*)d_in[1];
    const float* rrects = (const float*)d_in[2];
    float* out = (float*)d_out;

    const int SMEM3 = (P*4*2 + P*5) * (int)sizeof(float) + P*16*(int)sizeof(unsigned);
    cudaFuncSetAttribute(k3_nms,  cudaFuncAttributeMaxDynamicSharedMemorySize, SMEM3);

    k1_decode<<<NPROP, 32>>>(logits, regr, rrects);
    k2_sort<<<NGRP, P>>>();
    k3_nms<<<NGRP, P, SMEM3>>>();
    k4_topk<<<B, K4_THREADS>>>(out);
}